// round 13
// baseline (speedup 1.0000x reference)
#include <cuda_runtime.h>
#include <cstdint>
#include <cstddef>

#define HID     64
#define DIMH    128
#define DIMU    256
#define TROWS   16                        // rows per tile
#define CROWS   32                        // rows per CTA (2 tiles)
#define NWARP   16
#define THREADS 512
#define HPAD    132
#define BPAD    132
#define WSTR    132
#define BQ      (TROWS * BPAD)            // 2112: bases per k-quarter
#define HBUF    (TROWS * HPAD)            // 2112: one h buffer

// smem layout (float offsets)
#define OFF_W    0                        // Wc[128][WSTR] = 16896
#define OFF_H    (128 * WSTR)             // 16896: h[2][16][HPAD]
#define OFF_PAR  (OFF_H + 2 * HBUF)       // 21120
#define OFF_BASE (OFF_PAR + 452)          // 21572: bases[4][16][BPAD]
#define SMEM_FLOATS (OFF_BASE + 4 * BQ)   // 30020
#define SMEM_BYTES  (SMEM_FLOATS * 4)     // ~117.3 KB -> 1 CTA/SM

#define P_CU  0
#define P_CP0 64
#define P_CP1 128
#define P_B1U 192
#define P_B1P 256
#define P_W2U 320
#define P_W2P 384
#define P_B2  448

// HW-tanh GELU (MUFU.TANH): output rel err ~2e-4, passes 1e-3.
__device__ __forceinline__ float gelu_f(float x) {
  float x2 = x * x;
  float t  = fmaf(0.035677408136f, x2, 0.7978845608f);
  float a  = x * t;
  float th;
  asm("tanh.approx.f32 %0, %1;" : "=f"(th) : "f"(a));
  float hx = 0.5f * x;
  return fmaf(hx, th, hx);
}

__device__ __forceinline__ void cp16(uint32_t dst, const void* src) {
  asm volatile("cp.async.cg.shared.global [%0], [%1], 16;" :: "r"(dst), "l"(src));
}
__device__ __forceinline__ void cp4(uint32_t dst, const void* src) {
  asm volatile("cp.async.ca.shared.global [%0], [%1], 4;" :: "r"(dst), "l"(src));
}

// warp-level u count: a,b = 8 binary floats x 32 lanes (one 256-wide row).
// Returns warp-uniform {n1, c01, c10, c11} in f[0..3].
__device__ __forceinline__ void count_u(float4 a, float4 b, float* f) {
  int a0 = a.x > 0.5f, a1 = a.y > 0.5f, a2 = a.z > 0.5f, a3 = a.w > 0.5f;
  int e0 = b.x > 0.5f, e1 = b.y > 0.5f, e2 = b.z > 0.5f, e3 = b.w > 0.5f;
  int n1 = a0 + a1 + a2 + a3 + e0 + e1 + e2 + e3;
  const unsigned F = 0xffffffffu;
  const int lane = threadIdx.x & 31;
  int a0n  = __shfl_down_sync(F, a0, 1);
  int e0n  = __shfl_down_sync(F, e0, 1);
  int e0l0 = __shfl_sync(F, e0, 0);
  int c11 = 0, c10 = 0, c01 = 0;
#define ADDP(X, Y) { c11 += (X) & (Y); c10 += (X) & (1 ^ (Y)); c01 += (1 ^ (X)) & (Y); }
  ADDP(a0, a1) ADDP(a1, a2) ADDP(a2, a3)
  int xa = (lane < 31) ? a0n : e0l0;
  ADDP(a3, xa)
  ADDP(e0, e1) ADDP(e1, e2) ADDP(e2, e3)
  if (lane < 31) ADDP(e3, e0n)
#undef ADDP
  f[0] = (float)__reduce_add_sync(F, n1);
  f[1] = (float)__reduce_add_sync(F, c01);
  f[2] = (float)__reduce_add_sync(F, c10);
  f[3] = (float)__reduce_add_sync(F, c11);
}

extern __shared__ __align__(16) float sm[];

// GEMM for one tile: k-quarter kq = w>>2; thread = rows {rb, rb+8} x 8 j.
// jg = (w&3)*4 + (lane>>3); j-set = {jg + 16*jj}. All accesses conflict-free.
__device__ __forceinline__ void gemm_tile(int buf, int w, int lane) {
  const int kq = w >> 2;
  const int rb = lane & 7;
  const int jg = ((w & 3) << 2) + (lane >> 3);
  unsigned long long accA[8], accB[8];
#pragma unroll
  for (int jj = 0; jj < 8; jj++) { accA[jj] = 0ull; accB[jj] = 0ull; }
  const float* hA   = sm + OFF_H + buf * HBUF + rb * HPAD + kq * 32;
  const float* hB   = hA + 8 * HPAD;
  const float* wrow = sm + OFF_W + jg * WSTR + kq * 32;
#pragma unroll
  for (int k = 0; k < 32; k += 4) {
    ulonglong2 hvA = *reinterpret_cast<const ulonglong2*>(hA + k);
    ulonglong2 hvB = *reinterpret_cast<const ulonglong2*>(hB + k);
#pragma unroll
    for (int jj = 0; jj < 8; jj++) {
      ulonglong2 wv = *reinterpret_cast<const ulonglong2*>(wrow + jj * 16 * WSTR + k);
      asm("fma.rn.f32x2 %0, %1, %2, %0;" : "+l"(accA[jj]) : "l"(hvA.x), "l"(wv.x));
      asm("fma.rn.f32x2 %0, %1, %2, %0;" : "+l"(accA[jj]) : "l"(hvA.y), "l"(wv.y));
      asm("fma.rn.f32x2 %0, %1, %2, %0;" : "+l"(accB[jj]) : "l"(hvB.x), "l"(wv.x));
      asm("fma.rn.f32x2 %0, %1, %2, %0;" : "+l"(accB[jj]) : "l"(hvB.y), "l"(wv.y));
    }
  }
  float* dstA = sm + OFF_BASE + kq * BQ + rb * BPAD;
  float* dstB = dstA + 8 * BPAD;
#pragma unroll
  for (int jj = 0; jj < 8; jj++) {
    float lo, hi;
    asm("mov.b64 {%0, %1}, %2;" : "=f"(lo), "=f"(hi) : "l"(accA[jj]));
    dstA[jg + 16 * jj] = lo + hi;
    asm("mov.b64 {%0, %1}, %2;" : "=f"(lo), "=f"(hi) : "l"(accB[jj]));
    dstB[jg + 16 * jj] = lo + hi;
  }
}

// Epilogue for one tile: warp w = row w; lane handles 2 unary + 2 pairwise j.
__device__ __forceinline__ void epi_tile(const float* cnt, int w, int lane,
                                         float* out_row) {
  const int ju = lane * 2;
  const float n1 = cnt[0], c01 = cnt[1], c10 = cnt[2], c11 = cnt[3];
  const float c00 = 255.0f - c01 - c10 - c11;
  const float n0 = 256.0f - n1;
  const float* par = sm + OFF_PAR;
  const float* br  = sm + OFF_BASE + w * BPAD;

  float val = 0.f;
  // unary j = ju, ju+1
  {
    float2 s0 = *reinterpret_cast<const float2*>(br + ju);
    float2 s1 = *reinterpret_cast<const float2*>(br + BQ + ju);
    float2 s2 = *reinterpret_cast<const float2*>(br + 2 * BQ + ju);
    float2 s3 = *reinterpret_cast<const float2*>(br + 3 * BQ + ju);
    float2 bb = *reinterpret_cast<const float2*>(par + P_B1U + ju);
    float2 cu = *reinterpret_cast<const float2*>(par + P_CU  + ju);
    float2 w2 = *reinterpret_cast<const float2*>(par + P_W2U + ju);
    float bs0 = s0.x + s1.x + s2.x + s3.x + bb.x;
    float bs1 = s0.y + s1.y + s2.y + s3.y + bb.y;
    val += w2.x * (n0 * gelu_f(bs0) + n1 * gelu_f(bs0 + cu.x));
    val += w2.y * (n0 * gelu_f(bs1) + n1 * gelu_f(bs1 + cu.y));
  }
  // pairwise j = ju, ju+1 (bases at +64)
  {
    float2 s0 = *reinterpret_cast<const float2*>(br + 64 + ju);
    float2 s1 = *reinterpret_cast<const float2*>(br + BQ + 64 + ju);
    float2 s2 = *reinterpret_cast<const float2*>(br + 2 * BQ + 64 + ju);
    float2 s3 = *reinterpret_cast<const float2*>(br + 3 * BQ + 64 + ju);
    float2 bb = *reinterpret_cast<const float2*>(par + P_B1P + ju);
    float2 A2 = *reinterpret_cast<const float2*>(par + P_CP0 + ju);
    float2 B2 = *reinterpret_cast<const float2*>(par + P_CP1 + ju);
    float2 w2 = *reinterpret_cast<const float2*>(par + P_W2P + ju);
    float bs0 = s0.x + s1.x + s2.x + s3.x + bb.x;
    float bs1 = s0.y + s1.y + s2.y + s3.y + bb.y;
    val += w2.x * (c00 * gelu_f(bs0) + c01 * gelu_f(bs0 + B2.x)
                 + c10 * gelu_f(bs0 + A2.x) + c11 * gelu_f(bs0 + A2.x + B2.x));
    val += w2.y * (c00 * gelu_f(bs1) + c01 * gelu_f(bs1 + B2.y)
                 + c10 * gelu_f(bs1 + A2.y) + c11 * gelu_f(bs1 + A2.y + B2.y));
  }

  const unsigned F = 0xffffffffu;
  val += __shfl_xor_sync(F, val, 1);
  val += __shfl_xor_sync(F, val, 2);
  val += __shfl_xor_sync(F, val, 4);
  val += __shfl_xor_sync(F, val, 8);
  val += __shfl_xor_sync(F, val, 16);
  if (lane == 0)
    *out_row = val + 256.0f * par[P_B2] + 255.0f * par[P_B2 + 1];
}

__global__ void __launch_bounds__(THREADS, 1) fem_kernel(
    const float* __restrict__ u,   const float* __restrict__ h,
    const float* __restrict__ W1u, const float* __restrict__ b1u,
    const float* __restrict__ W2u, const float* __restrict__ b2u,
    const float* __restrict__ W1p, const float* __restrict__ b1p,
    const float* __restrict__ W2p, const float* __restrict__ b2p,
    float* __restrict__ out)
{
  const int tid  = threadIdx.x;
  const int lane = tid & 31;
  const int w    = tid >> 5;
  const int r0   = blockIdx.x * CROWS;
  const uint32_t smb = (uint32_t)__cvta_generic_to_shared(sm);

  // ---- 0) u loads for tile 0 first (warp w = row r0+w) ----
  float4 ua0, ub0;
  {
    const float4* u4 = reinterpret_cast<const float4*>(u);
    size_t base0 = (size_t)(r0 + w) * (DIMU / 4);
    ua0 = u4[base0 + lane];
    ub0 = u4[base0 + 32 + lane];
  }

  // ---- 1) group A: W (once for both tiles) + params + h0 ----
  {
    const int k  = tid & 127;
    const int j0 = tid >> 7;           // 0..3
    const float* srcU = W1u + (size_t)j0 * 129 + 1 + k;
    const float* srcP = W1p + (size_t)j0 * 130 + 2 + k;
    uint32_t dstU = smb + (uint32_t)(OFF_W + j0 * WSTR + k) * 4;
    uint32_t dstP = smb + (uint32_t)(OFF_W + (HID + j0) * WSTR + k) * 4;
#pragma unroll
    for (int it = 0; it < 16; it++) {
      cp4(dstU, srcU);  srcU += 4 * 129;  dstU += 4 * WSTR * 4;
      cp4(dstP, srcP);  srcP += 4 * 130;  dstP += 4 * WSTR * 4;
    }
  }
  if (tid < HID) {
    uint32_t pb = smb + OFF_PAR * 4;
    cp4(pb + (P_CU  + tid) * 4, W1u + (size_t)tid * 129);
    cp4(pb + (P_CP0 + tid) * 4, W1p + (size_t)tid * 130);
    cp4(pb + (P_CP1 + tid) * 4, W1p + (size_t)tid * 130 + 1);
    cp4(pb + (P_B1U + tid) * 4, b1u + tid);
    cp4(pb + (P_B1P + tid) * 4, b1p + tid);
    cp4(pb + (P_W2U + tid) * 4, W2u + tid);
    cp4(pb + (P_W2P + tid) * 4, W2p + tid);
    if (tid == 0) { cp4(pb + P_B2 * 4, b2u); cp4(pb + (P_B2 + 1) * 4, b2p); }
  }
  {
    const float4* h4 = reinterpret_cast<const float4*>(h) + (size_t)r0 * (DIMH / 4);
    int row = tid >> 5, c4 = tid & 31;     // 512 float4 = 1 per thread
    cp16(smb + (OFF_H + row * HPAD + c4 * 4) * 4, h4 + tid);
  }
  asm volatile("cp.async.commit_group;" ::: "memory");

  // ---- 2) group B: h1 ----
  {
    const float4* h4 = reinterpret_cast<const float4*>(h)
                     + (size_t)(r0 + TROWS) * (DIMH / 4);
    int row = tid >> 5, c4 = tid & 31;
    cp16(smb + (OFF_H + HBUF + row * HPAD + c4 * 4) * 4, h4 + tid);
  }
  asm volatile("cp.async.commit_group;" ::: "memory");

  // ---- 3) count u0 (regs, warp-uniform); prefetch u1 ----
  float cnt0[4];
  count_u(ua0, ub0, cnt0);
  float4 ua1, ub1;
  {
    const float4* u4 = reinterpret_cast<const float4*>(u);
    size_t base1 = (size_t)(r0 + TROWS + w) * (DIMU / 4);
    ua1 = u4[base1 + lane];              // latency hides under GEMM 0
    ub1 = u4[base1 + 32 + lane];
  }

  asm volatile("cp.async.wait_group 1;" ::: "memory");   // W, par, h0 ready
  __syncthreads();

  // ---- 4) tile 0 ----
  gemm_tile(0, w, lane);
  __syncthreads();
  epi_tile(cnt0, w, lane, out + r0 + w);

  // ---- 5) tile 1 ----
  float cnt1[4];
  count_u(ua1, ub1, cnt1);
  asm volatile("cp.async.wait_group 0;" ::: "memory");   // h1 ready (long since)
  __syncthreads();                        // bases reuse hazard: epi0 done
  gemm_tile(1, w, lane);
  __syncthreads();
  epi_tile(cnt1, w, lane, out + r0 + TROWS + w);
}

extern "C" void kernel_launch(void* const* d_in, const int* in_sizes, int n_in,
                              void* d_out, int out_size) {
  const float* u   = (const float*)d_in[0];
  const float* h   = (const float*)d_in[1];
  const float* W1u = (const float*)d_in[2];
  const float* b1u = (const float*)d_in[3];
  const float* W2u = (const float*)d_in[4];
  const float* b2u = (const float*)d_in[5];
  const float* W1p = (const float*)d_in[6];
  const float* b1p = (const float*)d_in[7];
  const float* W2p = (const float*)d_in[8];
  const float* b2p = (const float*)d_in[9];
  float* out = (float*)d_out;

  int B = in_sizes[1] / DIMH;   // 4096
  cudaFuncSetAttribute(fem_kernel, cudaFuncAttributeMaxDynamicSharedMemorySize, SMEM_BYTES);
  fem_kernel<<<B / CROWS, THREADS, SMEM_BYTES>>>(
      u, h, W1u, b1u, W2u, b2u, W1p, b1p, W2p, b2p, out);
}